// round 7
// baseline (speedup 1.0000x reference)
#include <cuda_runtime.h>
#include <mma.h>
#include <math.h>

using namespace nvcuda;

#define NN 50000
#define MP 50048   // padded rows: 391 * 128
#define NE 800000
#define NB1 196    // ceil(NN/256)

// ---------------- scratch ----------------
static __device__ int   d_cnt[NN];
static __device__ int   d_rowptr[NN + 1];
static __device__ int   d_cursor[NN];
static __device__ int   d_csrc[NE];
static __device__ int   d_part[256];
static __device__ float d_xp[(size_t)NN * 32];
static __device__ float d_mx[(size_t)MP * 48];
static __device__ float d_wc1[256 * 48];
static __device__ float d_h1[(size_t)MP * 256];
static __device__ float d_wc2[256 * 256];
static __device__ float d_pq2[(size_t)MP * 256];  // [p(128)|q(128)]
static __device__ float d_h2[(size_t)MP * 128];
static __device__ float d_wc3[128 * 128];
static __device__ float d_pq3[(size_t)MP * 128];  // [p(64)|q(64)]
static __device__ float d_h3[(size_t)MP * 64];
static __device__ float d_w1p[128 * 64];
static __device__ float d_y1[(size_t)MP * 128];
static __device__ float d_m1[256 * 13 * 11 * 11];
static __device__ float d_cg[896 * 128];
static __device__ float d_m2[128 * 891];
static __device__ float d_wmpart[8][64];
static __device__ float d_mnorm[64];
static __device__ float d_pmin[256];
static __device__ float d_pmax[256];
static __device__ float d_hstats[4];
static __device__ int   d_koff[6912];
static __device__ int   d_poff[896];

// ---------------- merged weight packing + conv gather tables ----------------
__global__ void k_packAll(const float* __restrict__ Wl1, const float* __restrict__ Wr1,
                          const float* __restrict__ Wl2, const float* __restrict__ Wr2,
                          const float* __restrict__ Wl3, const float* __restrict__ Wr3,
                          const float* __restrict__ W1) {
    int i = blockIdx.x * blockDim.x + threadIdx.x;
    if (i < 12288) {
        int n = i / 48, f = i % 48;
        float v = 0.f;
        if (f < 21) v = Wl1[n * 21 + f];
        else if (f < 42) v = Wr1[n * 21 + (f - 21)];
        d_wc1[i] = v;
    } else if (i < 77824) {
        int j = i - 12288;
        int n = j / 256, f = j % 256;
        d_wc2[j] = (n < 128) ? Wl2[n * 256 + f] : Wr2[(n - 128) * 256 + f];
    } else if (i < 94208) {
        int j = i - 77824;
        int n = j / 128, f = j % 128;
        d_wc3[j] = (n < 64) ? Wl3[n * 128 + f] : Wr3[(n - 64) * 128 + f];
    } else if (i < 102400) {
        int j = i - 94208;
        int n = j / 64;
        d_w1p[j] = (n < 64) ? W1[j] : 0.f;
    } else if (i < 109312) {
        int j = i - 102400;
        int ic = j / 27, tap = j % 27;
        int kd = tap / 9, r = tap % 9, kh = r / 3, kw = r % 3;
        d_koff[j] = ic * 1573 + kd * 121 + kh * 11 + kw;
    } else if (i < 110208) {
        int j = i - 109312;
        int v = 0;
        if (j < 891) {
            int od = j / 81, r2 = j % 81, oh = r2 / 9, ow = r2 % 9;
            v = od * 121 + oh * 11 + ow;
        }
        d_poff[j] = v;
    }
}

// ---------------- CSR build ----------------
__global__ void k_degcnt(const int* __restrict__ ei) {
    int e = blockIdx.x * blockDim.x + threadIdx.x;
    if (e < NE) atomicAdd(&d_cnt[ei[NE + e]], 1);
}
__global__ void k_scan1() {
    __shared__ int sh[256];
    int t = threadIdx.x;
    int i = blockIdx.x * 256 + t;
    int v = (i < NN) ? d_cnt[i] : 0;
    sh[t] = v;
    __syncthreads();
#pragma unroll
    for (int off = 1; off < 256; off <<= 1) {
        int a = (t >= off) ? sh[t - off] : 0;
        __syncthreads();
        sh[t] += a;
        __syncthreads();
    }
    if (i < NN) d_rowptr[i] = sh[t] - v;
    if (t == 255) d_part[blockIdx.x] = sh[255];
}
__global__ void k_scan3() {
    __shared__ int sh[256];
    int t = threadIdx.x;
    int v = (t < NB1) ? d_part[t] : 0;
    sh[t] = v;
    __syncthreads();
#pragma unroll
    for (int off = 1; off < 256; off <<= 1) {
        int a = (t >= off) ? sh[t - off] : 0;
        __syncthreads();
        sh[t] += a;
        __syncthreads();
    }
    int base = (blockIdx.x > 0) ? sh[blockIdx.x - 1] : 0;
    int i = blockIdx.x * 256 + t;
    if (i < NN) {
        int r = d_rowptr[i] + base;
        d_rowptr[i] = r;
        d_cursor[i] = r;
    }
    if (i == 0) d_rowptr[NN] = NE;
}
__global__ void k_scatter(const int* __restrict__ ei) {
    int e = blockIdx.x * blockDim.x + threadIdx.x;
    if (e >= NE) return;
    int s = ei[e], d = ei[NE + e];
    int pos = atomicAdd(&d_cursor[d], 1);
    d_csrc[pos] = s;
}

// ---------------- node feature pad + aggregation ----------------
__global__ void k_xpad(const float* __restrict__ x) {
    int idx = blockIdx.x * blockDim.x + threadIdx.x;
    if (idx >= NN * 32) return;
    int n = idx >> 5, f = idx & 31;
    d_xp[idx] = (f < 21) ? x[n * 21 + f] : 0.f;
}
__global__ void k_aggA() {
    int w = (blockIdx.x * blockDim.x + threadIdx.x) >> 5;
    int lane = threadIdx.x & 31;
    if (w >= NN) return;
    int beg = d_rowptr[w], end = d_rowptr[w + 1];
    float acc = 0.f;
    int e = beg;
    for (; e + 4 <= end; e += 4) {
        int s0 = __ldg(&d_csrc[e]);
        int s1 = __ldg(&d_csrc[e + 1]);
        int s2 = __ldg(&d_csrc[e + 2]);
        int s3 = __ldg(&d_csrc[e + 3]);
        acc += d_xp[(size_t)s0 * 32 + lane] + d_xp[(size_t)s1 * 32 + lane] +
               d_xp[(size_t)s2 * 32 + lane] + d_xp[(size_t)s3 * 32 + lane];
    }
    for (; e < end; e++) acc += d_xp[(size_t)__ldg(&d_csrc[e]) * 32 + lane];
    float inv = 1.f / fmaxf((float)(end - beg), 1.0f);
    if (lane < 21) {
        d_mx[(size_t)w * 48 + lane] = acc * inv;
        d_mx[(size_t)w * 48 + 21 + lane] = d_xp[(size_t)w * 32 + lane];
    } else if (lane < 27) {
        d_mx[(size_t)w * 48 + 21 + lane] = 0.f;
    }
}
__global__ void k_aggB(const float* __restrict__ bl) {
    int w = (blockIdx.x * blockDim.x + threadIdx.x) >> 5;
    int lane = threadIdx.x & 31;
    if (w >= NN) return;
    int beg = d_rowptr[w], end = d_rowptr[w + 1];
    const float4* pq = (const float4*)d_pq2;
    float4 acc = make_float4(0.f, 0.f, 0.f, 0.f);
#pragma unroll 4
    for (int e = beg; e < end; e++) {
        int s = __ldg(&d_csrc[e]);
        float4 v = pq[(size_t)s * 64 + lane];
        acc.x += v.x; acc.y += v.y; acc.z += v.z; acc.w += v.w;
    }
    float inv = 1.f / fmaxf((float)(end - beg), 1.0f);
    float4 q = pq[(size_t)w * 64 + 32 + lane];
    float4 b = ((const float4*)bl)[lane];
    float4 o;
    o.x = fmaxf(acc.x * inv + b.x + q.x, 0.f);
    o.y = fmaxf(acc.y * inv + b.y + q.y, 0.f);
    o.z = fmaxf(acc.z * inv + b.z + q.z, 0.f);
    o.w = fmaxf(acc.w * inv + b.w + q.w, 0.f);
    ((float4*)d_h2)[(size_t)w * 32 + lane] = o;
}
__global__ void k_aggC(const float* __restrict__ bl) {
    int g = (blockIdx.x * blockDim.x + threadIdx.x) >> 4;
    int lane = threadIdx.x & 15;
    if (g >= NN) return;
    int beg = d_rowptr[g], end = d_rowptr[g + 1];
    const float4* pq = (const float4*)d_pq3;
    float4 acc = make_float4(0.f, 0.f, 0.f, 0.f);
#pragma unroll 4
    for (int e = beg; e < end; e++) {
        int s = __ldg(&d_csrc[e]);
        float4 v = pq[(size_t)s * 32 + lane];
        acc.x += v.x; acc.y += v.y; acc.z += v.z; acc.w += v.w;
    }
    float inv = 1.f / fmaxf((float)(end - beg), 1.0f);
    float4 q = pq[(size_t)g * 32 + 16 + lane];
    float4 b = ((const float4*)bl)[lane];
    float4 o;
    o.x = acc.x * inv + b.x + q.x;
    o.y = acc.y * inv + b.y + q.y;
    o.z = acc.z * inv + b.z + q.z;
    o.w = acc.w * inv + b.w + q.w;
    ((float4*)d_h3)[(size_t)g * 16 + lane] = o;
}

// ---------------- tf32 tensor-core GEMM ----------------
// gather!=0: A[row][k] = d_m1[d_koff[k] + d_poff[row]]  (fused im2col)
__global__ void __launch_bounds__(256, 2) k_tgemm(
    const float* __restrict__ A, const float* __restrict__ B, float* __restrict__ C,
    int N, int K, const float* __restrict__ abias,
    const float* __restrict__ xstats, const float* __restrict__ madd,
    int split, int gather) {
    __shared__ float As[2][128][20];
    __shared__ float Bs[2][128][20];
    int tid = threadIdx.x;
    int wid = tid >> 5;
    int lane = tid & 31;
    int bm = blockIdx.y * 128;
    int bn = blockIdx.x * 128;
    int wm = (wid >> 2) * 64;
    int wn = (wid & 3) * 32;
    int lrow = tid >> 1;
    int lcol = (tid & 1) * 8;
    int nkz = (K / 16) / gridDim.z;
    int kbase = blockIdx.z * nkz * 16;

    float hs0 = 0.f, hs1 = 0.f;
    if (xstats) { hs0 = xstats[0]; hs1 = xstats[1]; }
    int prow = gather ? d_poff[bm + lrow] : 0;
    const int* gko = d_koff + kbase + lcol;

    wmma::fragment<wmma::accumulator, 16, 16, 8, float> cf[4][2];
#pragma unroll
    for (int i = 0; i < 4; i++)
#pragma unroll
        for (int j = 0; j < 2; j++) wmma::fill_fragment(cf[i][j], 0.f);

    const float* Arow = A + (size_t)(bm + lrow) * K + kbase + lcol;
    const float* Brow = B + (size_t)(bn + lrow) * K + kbase + lcol;

    float4 a0, a1, b0v, b1v;

#define CVT4(v)                                                                 \
    do {                                                                        \
        v.x = wmma::__float_to_tf32(v.x); v.y = wmma::__float_to_tf32(v.y);     \
        v.z = wmma::__float_to_tf32(v.z); v.w = wmma::__float_to_tf32(v.w);     \
    } while (0)

#define LOADTILE(koff)                                                          \
    do {                                                                        \
        if (gather) {                                                           \
            const int* kt = gko + (koff);                                       \
            a0.x = __ldg(&d_m1[kt[0] + prow]); a0.y = __ldg(&d_m1[kt[1] + prow]); \
            a0.z = __ldg(&d_m1[kt[2] + prow]); a0.w = __ldg(&d_m1[kt[3] + prow]); \
            a1.x = __ldg(&d_m1[kt[4] + prow]); a1.y = __ldg(&d_m1[kt[5] + prow]); \
            a1.z = __ldg(&d_m1[kt[6] + prow]); a1.w = __ldg(&d_m1[kt[7] + prow]); \
        } else {                                                                \
            a0 = *(const float4*)(Arow + (koff));                               \
            a1 = *(const float4*)(Arow + (koff) + 4);                           \
        }                                                                       \
        b0v = *(const float4*)(Brow + (koff));                                  \
        b1v = *(const float4*)(Brow + (koff) + 4);                              \
        if (abias) {                                                            \
            const float* bp = abias + (koff) + lcol;                            \
            a0.x = fmaxf(a0.x + bp[0], 0.f); a0.y = fmaxf(a0.y + bp[1], 0.f);   \
            a0.z = fmaxf(a0.z + bp[2], 0.f); a0.w = fmaxf(a0.w + bp[3], 0.f);   \
            a1.x = fmaxf(a1.x + bp[4], 0.f); a1.y = fmaxf(a1.y + bp[5], 0.f);   \
            a1.z = fmaxf(a1.z + bp[6], 0.f); a1.w = fmaxf(a1.w + bp[7], 0.f);   \
        } else if (xstats) {                                                    \
            const float* mp = madd + (koff) + lcol;                             \
            a0.x = hs0 * a0.x + hs1 + mp[0]; a0.y = hs0 * a0.y + hs1 + mp[1];   \
            a0.z = hs0 * a0.z + hs1 + mp[2]; a0.w = hs0 * a0.w + hs1 + mp[3];   \
            a1.x = hs0 * a1.x + hs1 + mp[4]; a1.y = hs0 * a1.y + hs1 + mp[5];   \
            a1.z = hs0 * a1.z + hs1 + mp[6]; a1.w = hs0 * a1.w + hs1 + mp[7];   \
        }                                                                       \
        CVT4(a0); CVT4(a1); CVT4(b0v); CVT4(b1v);                               \
    } while (0)

#define STORETILE(bi)                                                           \
    do {                                                                        \
        *(float4*)&As[bi][lrow][lcol] = a0;                                     \
        *(float4*)&As[bi][lrow][lcol + 4] = a1;                                 \
        *(float4*)&Bs[bi][lrow][lcol] = b0v;                                    \
        *(float4*)&Bs[bi][lrow][lcol + 4] = b1v;                                \
    } while (0)

    LOADTILE(0);
    STORETILE(0);
    __syncthreads();

    for (int it = 0; it < nkz; it++) {
        int buf = it & 1;
        bool more = (it + 1) < nkz;
        if (more) LOADTILE((it + 1) * 16);
#pragma unroll
        for (int ks = 0; ks < 16; ks += 8) {
            wmma::fragment<wmma::matrix_a, 16, 16, 8, wmma::precision::tf32, wmma::row_major> af[4];
            wmma::fragment<wmma::matrix_b, 16, 16, 8, wmma::precision::tf32, wmma::col_major> bf[2];
#pragma unroll
            for (int i = 0; i < 4; i++)
                wmma::load_matrix_sync(af[i], &As[buf][wm + i * 16][ks], 20);
#pragma unroll
            for (int j = 0; j < 2; j++)
                wmma::load_matrix_sync(bf[j], &Bs[buf][wn + j * 16][ks], 20);
#pragma unroll
            for (int i = 0; i < 4; i++)
#pragma unroll
                for (int j = 0; j < 2; j++)
                    wmma::mma_sync(cf[i][j], af[i], bf[j], cf[i][j]);
        }
        if (more) STORETILE(1 - buf);
        __syncthreads();
    }

    if (!split) {
#pragma unroll
        for (int i = 0; i < 4; i++)
#pragma unroll
            for (int j = 0; j < 2; j++)
                wmma::store_matrix_sync(&C[(size_t)(bm + wm + i * 16) * N + bn + wn + j * 16],
                                        cf[i][j], N, wmma::mem_row_major);
    } else {
        float* stage = &As[0][0][0] + wid * 320;
#pragma unroll
        for (int i = 0; i < 4; i++)
#pragma unroll
            for (int j = 0; j < 2; j++) {
                wmma::store_matrix_sync(stage, cf[i][j], 20, wmma::mem_row_major);
                __syncwarp();
                float* cp = &C[(size_t)(bm + wm + i * 16) * N + bn + wn + j * 16];
#pragma unroll
                for (int e = 0; e < 8; e++) {
                    int idx = lane * 8 + e;
                    int r = idx >> 4, c = idx & 15;
                    atomicAdd(&cp[(size_t)r * N + c], stage[r * 20 + c]);
                }
                __syncwarp();
            }
    }
#undef LOADTILE
#undef STORETILE
#undef CVT4
}

// ---------------- map encoder ----------------
__global__ void k_conv1(const float* __restrict__ in, const float* __restrict__ w,
                        const float* __restrict__ b) {
    int idx = blockIdx.x * blockDim.x + threadIdx.x;
    if (idx >= 256 * 1573) return;
    int oc = idx / 1573, p = idx % 1573;
    int od = p / 121, r = p % 121, oh = r / 11, ow = r % 11;
    const float* wp = w + oc * 75;
    float acc = 0.f;
#pragma unroll
    for (int kd = 0; kd < 3; kd++)
#pragma unroll
        for (int kh = 0; kh < 5; kh++)
#pragma unroll
            for (int kw = 0; kw < 5; kw++)
                acc += in[(od + kd) * 225 + (oh + kh) * 15 + (ow + kw)] *
                       wp[kd * 25 + kh * 5 + kw];
    d_m1[idx] = fmaxf(acc + b[oc], 0.f);
}

__global__ void k_m2fin(const float* __restrict__ cb2) {
    int idx = blockIdx.x * blockDim.x + threadIdx.x;
    if (idx >= 128 * 891) return;
    int oc = idx / 891, pos = idx % 891;
    d_m2[idx] = fmaxf(d_cg[(size_t)pos * 128 + oc] + cb2[oc], 0.f);
}

__global__ void k_wm(const float* __restrict__ Wm) {
    __shared__ float red[256];
    int o = blockIdx.x;
    int chunk = blockIdx.y;
    const int CH = 114048 / 8;
    int base = chunk * CH;
    const float* wr = Wm + (size_t)o * 114048 + base;
    const float* mv = d_m2 + base;
    float s = 0.f;
    for (int i = threadIdx.x * 4; i < CH; i += 256 * 4) {
        float4 a = *(const float4*)(wr + i);
        float4 v = *(const float4*)(mv + i);
        s += a.x * v.x + a.y * v.y + a.z * v.z + a.w * v.w;
    }
    red[threadIdx.x] = s;
    __syncthreads();
    for (int st = 128; st > 0; st >>= 1) {
        if (threadIdx.x < st) red[threadIdx.x] += red[threadIdx.x + st];
        __syncthreads();
    }
    if (threadIdx.x == 0) d_wmpart[chunk][o] = red[0];
}

// ---------------- h3 min/max ----------------
__global__ void k_hred1() {
    __shared__ float smn[256], smx[256];
    int tid = threadIdx.x;
    float mn = 3.4e38f, mx = -3.4e38f;
    for (size_t i = (size_t)blockIdx.x * 256 + tid; i < (size_t)NN * 64; i += (size_t)256 * 256) {
        float v = d_h3[i];
        mn = fminf(mn, v); mx = fmaxf(mx, v);
    }
    smn[tid] = mn; smx[tid] = mx;
    __syncthreads();
    for (int st = 128; st > 0; st >>= 1) {
        if (tid < st) {
            smn[tid] = fminf(smn[tid], smn[tid + st]);
            smx[tid] = fmaxf(smx[tid], smx[tid + st]);
        }
        __syncthreads();
    }
    if (tid == 0) { d_pmin[blockIdx.x] = smn[0]; d_pmax[blockIdx.x] = smx[0]; }
}
__global__ void k_finstats(const float* __restrict__ bm) {
    __shared__ float smn[256], smx[256];
    int t = threadIdx.x;
    smn[t] = d_pmin[t]; smx[t] = d_pmax[t];
    __syncthreads();
    for (int st = 128; st > 0; st >>= 1) {
        if (t < st) {
            smn[t] = fminf(smn[t], smn[t + st]);
            smx[t] = fmaxf(smx[t], smx[t + st]);
        }
        __syncthreads();
    }
    if (t == 0) {
        float mn = smn[0], mx = smx[0];
        float a = 0.35f / (mx - mn);
        d_hstats[0] = a;
        d_hstats[1] = -mn * a;
    }
    __syncthreads();
    float v = 0.f;
    if (t < 64) {
        v = bm[t];
#pragma unroll
        for (int c = 0; c < 8; c++) v += d_wmpart[c][t];
    }
    smn[t] = (t < 64) ? v : 3.4e38f;
    smx[t] = (t < 64) ? v : -3.4e38f;
    __syncthreads();
    for (int st = 128; st > 0; st >>= 1) {
        if (t < st) {
            smn[t] = fminf(smn[t], smn[t + st]);
            smx[t] = fmaxf(smx[t], smx[t + st]);
        }
        __syncthreads();
    }
    if (t < 64) {
        float mn = smn[0], mx = smx[0];
        d_mnorm[t] = 0.65f * (v - mn) / (mx - mn);
    }
}

// ---------------- final layer + softmax ----------------
__global__ void k_head(const float* __restrict__ W2, const float* __restrict__ b2,
                       const float* __restrict__ b1, float* __restrict__ out) {
    __shared__ float w2s[3][64];
    __shared__ float b2s[3];
    __shared__ float b1s[64];
    int tid = threadIdx.x;
    if (tid < 192) w2s[tid / 64][tid % 64] = W2[tid];
    if (tid < 3) b2s[tid] = b2[tid];
    if (tid >= 192 && tid < 256) b1s[tid - 192] = b1[tid - 192];
    __syncthreads();
    int i = blockIdx.x * blockDim.x + tid;
    if (i >= NN) return;
    const float* y = d_y1 + (size_t)i * 128;
    float s0 = b2s[0], s1 = b2s[1], s2 = b2s[2];
#pragma unroll
    for (int f = 0; f < 64; f += 4) {
        float4 v = *(const float4*)(y + f);
        v.x = fmaxf(v.x + b1s[f], 0.f);
        v.y = fmaxf(v.y + b1s[f + 1], 0.f);
        v.z = fmaxf(v.z + b1s[f + 2], 0.f);
        v.w = fmaxf(v.w + b1s[f + 3], 0.f);
        s0 += v.x * w2s[0][f] + v.y * w2s[0][f + 1] + v.z * w2s[0][f + 2] + v.w * w2s[0][f + 3];
        s1 += v.x * w2s[1][f] + v.y * w2s[1][f + 1] + v.z * w2s[1][f + 2] + v.w * w2s[1][f + 3];
        s2 += v.x * w2s[2][f] + v.y * w2s[2][f + 1] + v.z * w2s[2][f + 2] + v.w * w2s[2][f + 3];
    }
    float m = fmaxf(s0, fmaxf(s1, s2));
    float e0 = expf(s0 - m), e1 = expf(s1 - m), e2 = expf(s2 - m);
    float inv = 1.f / (e0 + e1 + e2);
    out[(size_t)i * 3 + 0] = e0 * inv;
    out[(size_t)i * 3 + 1] = e1 * inv;
    out[(size_t)i * 3 + 2] = e2 * inv;
}

// ---------------- launch ----------------
extern "C" void kernel_launch(void* const* d_in, const int* in_sizes, int n_in,
                              void* d_out, int out_size) {
    (void)in_sizes; (void)n_in; (void)out_size;
    const float* node = (const float*)d_in[0];
    const int* ei = (const int*)d_in[1];
    const float* mapd = (const float*)d_in[2];
    const float* bl1 = (const float*)d_in[4];
    const float* bl2 = (const float*)d_in[7];
    const float* bl3 = (const float*)d_in[10];
    const float* k1 = (const float*)d_in[12];
    const float* cb1 = (const float*)d_in[13];
    const float* k2 = (const float*)d_in[14];
    const float* cb2 = (const float*)d_in[15];
    const float* Wm = (const float*)d_in[16];
    const float* bm = (const float*)d_in[17];
    const float* b1 = (const float*)d_in[19];
    const float* W2 = (const float*)d_in[20];
    const float* b2 = (const float*)d_in[21];
    float* out = (float*)d_out;

    void *p_cnt, *p_cg;
    void *p_mx, *p_wc1, *p_h1, *p_wc2, *p_pq2, *p_h2, *p_wc3, *p_pq3, *p_h3;
    void *p_w1p, *p_y1, *p_hstats, *p_mnorm;
    cudaGetSymbolAddress(&p_cnt, d_cnt);
    cudaGetSymbolAddress(&p_cg, d_cg);
    cudaGetSymbolAddress(&p_mx, d_mx);
    cudaGetSymbolAddress(&p_wc1, d_wc1);
    cudaGetSymbolAddress(&p_h1, d_h1);
    cudaGetSymbolAddress(&p_wc2, d_wc2);
    cudaGetSymbolAddress(&p_pq2, d_pq2);
    cudaGetSymbolAddress(&p_h2, d_h2);
    cudaGetSymbolAddress(&p_wc3, d_wc3);
    cudaGetSymbolAddress(&p_pq3, d_pq3);
    cudaGetSymbolAddress(&p_h3, d_h3);
    cudaGetSymbolAddress(&p_w1p, d_w1p);
    cudaGetSymbolAddress(&p_y1, d_y1);
    cudaGetSymbolAddress(&p_hstats, d_hstats);
    cudaGetSymbolAddress(&p_mnorm, d_mnorm);

    // 1: memset(cnt)  2: memset(cg)
    cudaMemsetAsync(p_cnt, 0, NN * sizeof(int));
    cudaMemsetAsync(p_cg, 0, 896 * 128 * sizeof(float));

    // 3: packAll  4: conv1  5: degcnt  6: conv2 gather-GEMM (ncu target)
    k_packAll<<<431, 256>>>((const float*)d_in[3], (const float*)d_in[5],
                            (const float*)d_in[6], (const float*)d_in[8],
                            (const float*)d_in[9], (const float*)d_in[11],
                            (const float*)d_in[18]);
    k_conv1<<<(256 * 1573 + 255) / 256, 256>>>(mapd, k1, cb1);
    k_degcnt<<<(NE + 255) / 256, 256>>>(ei);
    k_tgemm<<<dim3(1, 7, 48), 256>>>(nullptr, k2, (float*)p_cg,
                                     128, 6912, nullptr, nullptr, nullptr, 1, 1);
    k_m2fin<<<(128 * 891 + 255) / 256, 256>>>(cb2);
    k_wm<<<dim3(64, 8), 256>>>(Wm);

    // CSR build (degcnt already issued above)
    k_scan1<<<NB1, 256>>>();
    k_scan3<<<NB1, 256>>>();
    k_scatter<<<(NE + 255) / 256, 256>>>(ei);

    // layer 1
    k_xpad<<<(NN * 32 + 255) / 256, 256>>>(node);
    k_aggA<<<(NN * 32 + 255) / 256, 256>>>();
    k_tgemm<<<dim3(2, 391, 1), 256>>>((const float*)p_mx, (const float*)p_wc1,
                                      (float*)p_h1, 256, 48,
                                      nullptr, nullptr, nullptr, 0, 0);
    // layer 2
    k_tgemm<<<dim3(2, 391, 1), 256>>>((const float*)p_h1, (const float*)p_wc2,
                                      (float*)p_pq2, 256, 256,
                                      bl1, nullptr, nullptr, 0, 0);
    k_aggB<<<(NN * 32 + 255) / 256, 256>>>(bl2);
    // layer 3
    k_tgemm<<<dim3(1, 391, 1), 256>>>((const float*)p_h2, (const float*)p_wc3,
                                      (float*)p_pq3, 128, 128,
                                      nullptr, nullptr, nullptr, 0, 0);
    k_aggC<<<(NN * 16 + 255) / 256, 256>>>(bl3);

    // stats + head
    k_hred1<<<256, 256>>>();
    k_finstats<<<1, 256>>>(bm);
    k_tgemm<<<dim3(1, 391, 1), 256>>>((const float*)p_h3, (const float*)p_w1p,
                                      (float*)p_y1, 128, 64,
                                      nullptr, (const float*)p_hstats,
                                      (const float*)p_mnorm, 0, 0);
    k_head<<<(NN + 255) / 256, 256>>>(W2, b2, b1, out);
}

// round 8
// speedup vs baseline: 1.0003x; 1.0003x over previous
#include <cuda_runtime.h>
#include <mma.h>
#include <math.h>

using namespace nvcuda;

#define NN 50000
#define MP 50048   // padded rows: 391 * 128
#define NE 800000
#define NB1 196    // ceil(NN/256)
#define TG_SMEM 73728  // 4 * 128 * 36 * 4 bytes (A+B double-buffered, BK=32)

// ---------------- scratch ----------------
static __device__ int   d_cnt[NN];
static __device__ int   d_rowptr[NN + 1];
static __device__ int   d_cursor[NN];
static __device__ int   d_csrc[NE];
static __device__ int   d_part[256];
static __device__ float d_xp[(size_t)NN * 32];
static __device__ float d_mx[(size_t)MP * 64];    // [mean(21)|x(21)|pad(22)]
static __device__ float d_wc1[256 * 64];
static __device__ float d_h1[(size_t)MP * 256];
static __device__ float d_wc2[256 * 256];
static __device__ float d_pq2[(size_t)MP * 256];  // [p(128)|q(128)]
static __device__ float d_h2[(size_t)MP * 128];
static __device__ float d_wc3[128 * 128];
static __device__ float d_pq3[(size_t)MP * 128];  // [p(64)|q(64)]
static __device__ float d_h3[(size_t)MP * 64];
static __device__ float d_w1p[128 * 64];
static __device__ float d_y1[(size_t)MP * 128];
static __device__ float d_m1[256 * 13 * 11 * 11];
static __device__ float d_xcol[(size_t)896 * 6912];
static __device__ float d_cg[896 * 128];
static __device__ float d_m2[128 * 891];
static __device__ float d_wmpart[8][64];
static __device__ float d_mnorm[64];
static __device__ float d_pmin[256];
static __device__ float d_pmax[256];
static __device__ float d_hstats[4];
static __device__ int   d_koff[6912];
static __device__ int   d_poff[896];

// ---------------- merged weight packing + im2col tables ----------------
// [0,16384): wc1  [16384,81920): wc2  [81920,98304): wc3  [98304,106496): w1p
// [106496,113408): koff  [113408,114304): poff
__global__ void k_packAll(const float* __restrict__ Wl1, const float* __restrict__ Wr1,
                          const float* __restrict__ Wl2, const float* __restrict__ Wr2,
                          const float* __restrict__ Wl3, const float* __restrict__ Wr3,
                          const float* __restrict__ W1) {
    int i = blockIdx.x * blockDim.x + threadIdx.x;
    if (i < 16384) {
        int n = i / 64, f = i % 64;
        float v = 0.f;
        if (f < 21) v = Wl1[n * 21 + f];
        else if (f < 42) v = Wr1[n * 21 + (f - 21)];
        d_wc1[i] = v;
    } else if (i < 81920) {
        int j = i - 16384;
        int n = j / 256, f = j % 256;
        d_wc2[j] = (n < 128) ? Wl2[n * 256 + f] : Wr2[(n - 128) * 256 + f];
    } else if (i < 98304) {
        int j = i - 81920;
        int n = j / 128, f = j % 128;
        d_wc3[j] = (n < 64) ? Wl3[n * 128 + f] : Wr3[(n - 64) * 128 + f];
    } else if (i < 106496) {
        int j = i - 98304;
        int n = j / 64;
        d_w1p[j] = (n < 64) ? W1[j] : 0.f;
    } else if (i < 113408) {
        int j = i - 106496;
        int ic = j / 27, tap = j % 27;
        int kd = tap / 9, r = tap % 9, kh = r / 3, kw = r % 3;
        d_koff[j] = ic * 1573 + kd * 121 + kh * 11 + kw;
    } else if (i < 114304) {
        int j = i - 113408;
        int v = 0;
        if (j < 891) {
            int od = j / 81, r2 = j % 81, oh = r2 / 9, ow = r2 % 9;
            v = od * 121 + oh * 11 + ow;
        }
        d_poff[j] = v;
    }
}

// ---------------- CSR build ----------------
__global__ void k_degcnt(const int* __restrict__ ei) {
    int e = blockIdx.x * blockDim.x + threadIdx.x;
    if (e < NE) atomicAdd(&d_cnt[ei[NE + e]], 1);
}
__global__ void k_scan1() {
    __shared__ int sh[256];
    int t = threadIdx.x;
    int i = blockIdx.x * 256 + t;
    int v = (i < NN) ? d_cnt[i] : 0;
    sh[t] = v;
    __syncthreads();
#pragma unroll
    for (int off = 1; off < 256; off <<= 1) {
        int a = (t >= off) ? sh[t - off] : 0;
        __syncthreads();
        sh[t] += a;
        __syncthreads();
    }
    if (i < NN) d_rowptr[i] = sh[t] - v;
    if (t == 255) d_part[blockIdx.x] = sh[255];
}
__global__ void k_scan3() {
    __shared__ int sh[256];
    int t = threadIdx.x;
    int v = (t < NB1) ? d_part[t] : 0;
    sh[t] = v;
    __syncthreads();
#pragma unroll
    for (int off = 1; off < 256; off <<= 1) {
        int a = (t >= off) ? sh[t - off] : 0;
        __syncthreads();
        sh[t] += a;
        __syncthreads();
    }
    int base = (blockIdx.x > 0) ? sh[blockIdx.x - 1] : 0;
    int i = blockIdx.x * 256 + t;
    if (i < NN) {
        int r = d_rowptr[i] + base;
        d_rowptr[i] = r;
        d_cursor[i] = r;
    }
    if (i == 0) d_rowptr[NN] = NE;
}
__global__ void k_scatter(const int* __restrict__ ei) {
    int e = blockIdx.x * blockDim.x + threadIdx.x;
    if (e >= NE) return;
    int s = ei[e], d = ei[NE + e];
    int pos = atomicAdd(&d_cursor[d], 1);
    d_csrc[pos] = s;
}

// ---------------- node feature pad + aggregation ----------------
__global__ void k_xpad(const float* __restrict__ x) {
    int idx = blockIdx.x * blockDim.x + threadIdx.x;
    if (idx >= NN * 32) return;
    int n = idx >> 5, f = idx & 31;
    d_xp[idx] = (f < 21) ? x[n * 21 + f] : 0.f;
}
// warp per node; writes 64-wide padded row [mean(21)|x(21)|0...]
__global__ void k_aggA() {
    int w = (blockIdx.x * blockDim.x + threadIdx.x) >> 5;
    int lane = threadIdx.x & 31;
    if (w >= NN) return;
    int beg = d_rowptr[w], end = d_rowptr[w + 1];
    float acc = 0.f;
    int e = beg;
    for (; e + 4 <= end; e += 4) {
        int s0 = __ldg(&d_csrc[e]);
        int s1 = __ldg(&d_csrc[e + 1]);
        int s2 = __ldg(&d_csrc[e + 2]);
        int s3 = __ldg(&d_csrc[e + 3]);
        acc += d_xp[(size_t)s0 * 32 + lane] + d_xp[(size_t)s1 * 32 + lane] +
               d_xp[(size_t)s2 * 32 + lane] + d_xp[(size_t)s3 * 32 + lane];
    }
    for (; e < end; e++) acc += d_xp[(size_t)__ldg(&d_csrc[e]) * 32 + lane];
    float inv = 1.f / fmaxf((float)(end - beg), 1.0f);
    float xo = d_xp[(size_t)w * 32 + lane];  // own feature (0 for lane>=21)
    // col lane:      mean[lane] (lane<21) else x[lane-21] (lane 21..31)
    // col lane+32:   x[lane+11] (lane<10) else 0
    float v1 = __shfl_sync(0xffffffffu, xo, (lane >= 21) ? (lane - 21) : 0);
    if (lane < 21) v1 = acc * inv;
    float v2 = __shfl_sync(0xffffffffu, xo, (lane + 11) & 31);
    if (lane >= 10) v2 = 0.f;
    d_mx[(size_t)w * 64 + lane] = v1;
    d_mx[(size_t)w * 64 + 32 + lane] = v2;
}
__global__ void k_aggB(const float* __restrict__ bl) {
    int w = (blockIdx.x * blockDim.x + threadIdx.x) >> 5;
    int lane = threadIdx.x & 31;
    if (w >= NN) return;
    int beg = d_rowptr[w], end = d_rowptr[w + 1];
    const float4* pq = (const float4*)d_pq2;
    float4 acc = make_float4(0.f, 0.f, 0.f, 0.f);
#pragma unroll 4
    for (int e = beg; e < end; e++) {
        int s = __ldg(&d_csrc[e]);
        float4 v = pq[(size_t)s * 64 + lane];
        acc.x += v.x; acc.y += v.y; acc.z += v.z; acc.w += v.w;
    }
    float inv = 1.f / fmaxf((float)(end - beg), 1.0f);
    float4 q = pq[(size_t)w * 64 + 32 + lane];
    float4 b = ((const float4*)bl)[lane];
    float4 o;
    o.x = fmaxf(acc.x * inv + b.x + q.x, 0.f);
    o.y = fmaxf(acc.y * inv + b.y + q.y, 0.f);
    o.z = fmaxf(acc.z * inv + b.z + q.z, 0.f);
    o.w = fmaxf(acc.w * inv + b.w + q.w, 0.f);
    ((float4*)d_h2)[(size_t)w * 32 + lane] = o;
}
__global__ void k_aggC(const float* __restrict__ bl) {
    int g = (blockIdx.x * blockDim.x + threadIdx.x) >> 4;
    int lane = threadIdx.x & 15;
    if (g >= NN) return;
    int beg = d_rowptr[g], end = d_rowptr[g + 1];
    const float4* pq = (const float4*)d_pq3;
    float4 acc = make_float4(0.f, 0.f, 0.f, 0.f);
#pragma unroll 4
    for (int e = beg; e < end; e++) {
        int s = __ldg(&d_csrc[e]);
        float4 v = pq[(size_t)s * 32 + lane];
        acc.x += v.x; acc.y += v.y; acc.z += v.z; acc.w += v.w;
    }
    float inv = 1.f / fmaxf((float)(end - beg), 1.0f);
    float4 q = pq[(size_t)g * 32 + 16 + lane];
    float4 b = ((const float4*)bl)[lane];
    float4 o;
    o.x = acc.x * inv + b.x + q.x;
    o.y = acc.y * inv + b.y + q.y;
    o.z = acc.z * inv + b.z + q.z;
    o.w = acc.w * inv + b.w + q.w;
    ((float4*)d_h3)[(size_t)g * 16 + lane] = o;
}

// ---------------- tf32 tensor-core GEMM (BK=32, dynamic smem, double-buffered) --
// C[.,N] = A[.,K] @ B[N,K]^T.  K % 32 == 0, (K/32) % gridDim.z == 0.
// Staged load order (A loads -> A store -> B loads -> mma -> B store) caps live regs.
__global__ void __launch_bounds__(256, 2) k_tgemm(
    const float* __restrict__ A, const float* __restrict__ B, float* __restrict__ C,
    int N, int K, const float* __restrict__ abias,
    const float* __restrict__ xstats, const float* __restrict__ madd, int split) {
    extern __shared__ float smem[];
    float* Asm = smem;                  // [2][128][36]
    float* Bsm = smem + 2 * 128 * 36;   // [2][128][36]
    const int TS = 128 * 36;
    int tid = threadIdx.x;
    int wid = tid >> 5;
    int lane = tid & 31;
    int bm = blockIdx.y * 128;
    int bn = blockIdx.x * 128;
    int wm = (wid >> 2) * 64;
    int wn = (wid & 3) * 32;
    int lrow = tid >> 1;
    int lcol = (tid & 1) * 16;
    int nkz = (K / 32) / gridDim.z;
    int kbase = blockIdx.z * nkz * 32;

    float hs0 = 0.f, hs1 = 0.f;
    if (xstats) { hs0 = xstats[0]; hs1 = xstats[1]; }

    wmma::fragment<wmma::accumulator, 16, 16, 8, float> cf[4][2];
#pragma unroll
    for (int i = 0; i < 4; i++)
#pragma unroll
        for (int j = 0; j < 2; j++) wmma::fill_fragment(cf[i][j], 0.f);

    const float* Arow = A + (size_t)(bm + lrow) * K + kbase + lcol;
    const float* Brow = B + (size_t)(bn + lrow) * K + kbase + lcol;
    float* AsRow = Asm + lrow * 36 + lcol;
    float* BsRow = Bsm + lrow * 36 + lcol;

    float4 ra[4], rb[4];

#define CVT4(v)                                                                 \
    do {                                                                        \
        v.x = wmma::__float_to_tf32(v.x); v.y = wmma::__float_to_tf32(v.y);     \
        v.z = wmma::__float_to_tf32(v.z); v.w = wmma::__float_to_tf32(v.w);     \
    } while (0)

#define LOADA(koff)                                                             \
    do {                                                                        \
        _Pragma("unroll")                                                       \
        for (int u = 0; u < 4; u++) ra[u] = *(const float4*)(Arow + (koff) + u * 4); \
        if (abias) {                                                            \
            const float* bp = abias + kbase + (koff) + lcol;                    \
            _Pragma("unroll")                                                   \
            for (int u = 0; u < 4; u++) {                                       \
                ra[u].x = fmaxf(ra[u].x + bp[u * 4 + 0], 0.f);                  \
                ra[u].y = fmaxf(ra[u].y + bp[u * 4 + 1], 0.f);                  \
                ra[u].z = fmaxf(ra[u].z + bp[u * 4 + 2], 0.f);                  \
                ra[u].w = fmaxf(ra[u].w + bp[u * 4 + 3], 0.f);                  \
            }                                                                   \
        } else if (xstats) {                                                    \
            const float* mp = madd + kbase + (koff) + lcol;                     \
            _Pragma("unroll")                                                   \
            for (int u = 0; u < 4; u++) {                                       \
                ra[u].x = hs0 * ra[u].x + hs1 + mp[u * 4 + 0];                  \
                ra[u].y = hs0 * ra[u].y + hs1 + mp[u * 4 + 1];                  \
                ra[u].z = hs0 * ra[u].z + hs1 + mp[u * 4 + 2];                  \
                ra[u].w = hs0 * ra[u].w + hs1 + mp[u * 4 + 3];                  \
            }                                                                   \
        }                                                                       \
        CVT4(ra[0]); CVT4(ra[1]); CVT4(ra[2]); CVT4(ra[3]);                     \
    } while (0)

#define LOADB(koff)                                                             \
    do {                                                                        \
        _Pragma("unroll")                                                       \
        for (int u = 0; u < 4; u++) rb[u] = *(const float4*)(Brow + (koff) + u * 4); \
        CVT4(rb[0]); CVT4(rb[1]); CVT4(rb[2]); CVT4(rb[3]);                     \
    } while (0)

#define STA(bi)                                                                 \
    do { _Pragma("unroll")                                                      \
         for (int u = 0; u < 4; u++) *(float4*)(AsRow + (bi) * TS + u * 4) = ra[u]; } while (0)
#define STB(bi)                                                                 \
    do { _Pragma("unroll")                                                      \
         for (int u = 0; u < 4; u++) *(float4*)(BsRow + (bi) * TS + u * 4) = rb[u]; } while (0)

    LOADA(0); STA(0);
    LOADB(0); STB(0);
    __syncthreads();

    for (int it = 0; it < nkz; it++) {
        int buf = it & 1;
        bool more = (it + 1) < nkz;
        if (more) { LOADA((it + 1) * 32); STA(1 - buf); LOADB((it + 1) * 32); }
#pragma unroll
        for (int ks = 0; ks < 32; ks += 8) {
            wmma::fragment<wmma::matrix_a, 16, 16, 8, wmma::precision::tf32, wmma::row_major> af[4];
            wmma::fragment<wmma::matrix_b, 16, 16, 8, wmma::precision::tf32, wmma::col_major> bf[2];
#pragma unroll
            for (int i = 0; i < 4; i++)
                wmma::load_matrix_sync(af[i], Asm + buf * TS + (wm + i * 16) * 36 + ks, 36);
#pragma unroll
            for (int j = 0; j < 2; j++)
                wmma::load_matrix_sync(bf[j], Bsm + buf * TS + (wn + j * 16) * 36 + ks, 36);
#pragma unroll
            for (int i = 0; i < 4; i++)
#pragma unroll
                for (int j = 0; j < 2; j++)
                    wmma::mma_sync(cf[i][j], af[i], bf[j], cf[i][j]);
        }
        if (more) STB(1 - buf);
        __syncthreads();
    }

    if (!split) {
#pragma unroll
        for (int i = 0; i < 4; i++)
#pragma unroll
            for (int j = 0; j < 2; j++)
                wmma::store_matrix_sync(&C[(size_t)(bm + wm + i * 16) * N + bn + wn + j * 16],
                                        cf[i][j], N, wmma::mem_row_major);
    } else {
        float* stage = Asm + wid * 320;
#pragma unroll
        for (int i = 0; i < 4; i++)
#pragma unroll
            for (int j = 0; j < 2; j++) {
                wmma::store_matrix_sync(stage, cf[i][j], 20, wmma::mem_row_major);
                __syncwarp();
                float* cp = &C[(size_t)(bm + wm + i * 16) * N + bn + wn + j * 16];
#pragma unroll
                for (int e = 0; e < 8; e++) {
                    int idx = lane * 8 + e;
                    int r = idx >> 4, c = idx & 15;
                    atomicAdd(&cp[(size_t)r * N + c], stage[r * 20 + c]);
                }
                __syncwarp();
            }
    }
#undef LOADA
#undef LOADB
#undef STA
#undef STB
#undef CVT4
}

// ---------------- map encoder ----------------
__global__ void k_conv1(const float* __restrict__ in, const float* __restrict__ w,
                        const float* __restrict__ b) {
    int idx = blockIdx.x * blockDim.x + threadIdx.x;
    if (idx >= 256 * 1573) return;
    int oc = idx / 1573, p = idx % 1573;
    int od = p / 121, r = p % 121, oh = r / 11, ow = r % 11;
    const float* wp = w + oc * 75;
    float acc = 0.f;
#pragma unroll
    for (int kd = 0; kd < 3; kd++)
#pragma unroll
        for (int kh = 0; kh < 5; kh++)
#pragma unroll
            for (int kw = 0; kw < 5; kw++)
                acc += in[(od + kd) * 225 + (oh + kh) * 15 + (ow + kw)] *
                       wp[kd * 25 + kh * 5 + kw];
    d_m1[idx] = fmaxf(acc + b[oc], 0.f);
}

__global__ void k_im2col() {
    int k = blockIdx.x * 256 + threadIdx.x;
    int pos = blockIdx.y;
    d_xcol[(size_t)pos * 6912 + k] = d_m1[d_koff[k] + d_poff[pos]];
}

__global__ void k_m2fin(const float* __restrict__ cb2) {
    int idx = blockIdx.x * blockDim.x + threadIdx.x;
    if (idx >= 128 * 891) return;
    int oc = idx / 891, pos = idx % 891;
    d_m2[idx] = fmaxf(d_cg[(size_t)pos * 128 + oc] + cb2[oc], 0.f);
}

__global__ void k_wm(const float* __restrict__ Wm) {
    __shared__ float red[256];
    int o = blockIdx.x;
    int chunk = blockIdx.y;
    const int CH = 114048 / 8;
    int base = chunk * CH;
    const float* wr = Wm + (size_t)o * 114048 + base;
    const float* mv = d_m2 + base;
    float s = 0.f;
    for (int i = threadIdx.x * 4; i < CH; i += 256 * 4) {
        float4 a = *(const float4*)(wr + i);
        float4 v = *(const float4*)(mv + i);
        s += a.x * v.x + a.y * v.y + a.z * v.z + a.w * v.w;
    }
    red[threadIdx.x] = s;
    __syncthreads();
    for (int st = 128; st > 0; st >>= 1) {
        if (threadIdx.x < st) red[threadIdx.x] += red[threadIdx.x + st];
        __syncthreads();
    }
    if (threadIdx.x == 0) d_wmpart[chunk][o] = red[0];
}

// ---------------- h3 min/max ----------------
__global__ void k_hred1() {
    __shared__ float smn[256], smx[256];
    int tid = threadIdx.x;
    float mn = 3.4e38f, mx = -3.4e38f;
    for (size_t i = (size_t)blockIdx.x * 256 + tid; i < (size_t)NN * 64; i += (size_t)256 * 256) {
        float v = d_h3[i];
        mn = fminf(mn, v); mx = fmaxf(mx, v);
    }
    smn[tid] = mn; smx[tid] = mx;
    __syncthreads();
    for (int st = 128; st > 0; st >>= 1) {
        if (tid < st) {
            smn[tid] = fminf(smn[tid], smn[tid + st]);
            smx[tid] = fmaxf(smx[tid], smx[tid + st]);
        }
        __syncthreads();
    }
    if (tid == 0) { d_pmin[blockIdx.x] = smn[0]; d_pmax[blockIdx.x] = smx[0]; }
}
__global__ void k_finstats(const float* __restrict__ bm) {
    __shared__ float smn[256], smx[256];
    int t = threadIdx.x;
    smn[t] = d_pmin[t]; smx[t] = d_pmax[t];
    __syncthreads();
    for (int st = 128; st > 0; st >>= 1) {
        if (t < st) {
            smn[t] = fminf(smn[t], smn[t + st]);
            smx[t] = fmaxf(smx[t], smx[t + st]);
        }
        __syncthreads();
    }
    if (t == 0) {
        float mn = smn[0], mx = smx[0];
        float a = 0.35f / (mx - mn);
        d_hstats[0] = a;
        d_hstats[1] = -mn * a;
    }
    __syncthreads();
    float v = 0.f;
    if (t < 64) {
        v = bm[t];
#pragma unroll
        for (int c = 0; c < 8; c++) v += d_wmpart[c][t];
    }
    smn[t] = (t < 64) ? v : 3.4e38f;
    smx[t] = (t < 64) ? v : -3.4e38f;
    __syncthreads();
    for (int st = 128; st > 0; st >>= 1) {
        if (t < st) {
            smn[t] = fminf(smn[t], smn[t + st]);
            smx[t] = fmaxf(smx[t], smx[t + st]);
        }
        __syncthreads();
    }
    if (t < 64) {
        float mn = smn[0], mx = smx[0];
        d_mnorm[t] = 0.65f * (v - mn) / (mx - mn);
    }
}

// ---------------- final layer + softmax ----------------
__global__ void k_head(const float* __restrict__ W2, const float* __restrict__ b2,
                       const float* __restrict__ b1, float* __restrict__ out) {
    __shared__ float w2s[3][64];
    __shared__ float b2s[3];
    __shared__ float b1s[64];
    int tid = threadIdx.x;
    if (tid < 192) w2s[tid / 64][tid % 64] = W2[tid];
    if (tid < 3) b2s[tid] = b2[tid];
    if (tid >= 192 && tid < 256) b1s[tid - 192] = b1[tid - 192];
    __syncthreads();
    int i = blockIdx.x * blockDim.x + tid;
    if (i >= NN) return;
    const float* y = d_y1 + (size_t)i * 128;
    float s0 = b2s[0], s1 = b2s[1], s2 = b2s[2];
#pragma unroll
    for (int f = 0; f < 64; f += 4) {
        float4 v = *(const float4*)(y + f);
        v.x = fmaxf(v.x + b1s[f], 0.f);
        v.y = fmaxf(v.y + b1s[f + 1], 0.f);
        v.z = fmaxf(v.z + b1s[f + 2], 0.f);
        v.w = fmaxf(v.w + b1s[f + 3], 0.f);
        s0 += v.x * w2s[0][f] + v.y * w2s[0][f + 1] + v.z * w2s[0][f + 2] + v.w * w2s[0][f + 3];
        s1 += v.x * w2s[1][f] + v.y * w2s[1][f + 1] + v.z * w2s[1][f + 2] + v.w * w2s[1][f + 3];
        s2 += v.x * w2s[2][f] + v.y * w2s[2][f + 1] + v.z * w2s[2][f + 2] + v.w * w2s[2][f + 3];
    }
    float m = fmaxf(s0, fmaxf(s1, s2));
    float e0 = expf(s0 - m), e1 = expf(s1 - m), e2 = expf(s2 - m);
    float inv = 1.f / (e0 + e1 + e2);
    out[(size_t)i * 3 + 0] = e0 * inv;
    out[(size_t)i * 3 + 1] = e1 * inv;
    out[(size_t)i * 3 + 2] = e2 * inv;
}

// ---------------- launch ----------------
extern "C" void kernel_launch(void* const* d_in, const int* in_sizes, int n_in,
                              void* d_out, int out_size) {
    (void)in_sizes; (void)n_in; (void)out_size;
    const float* node = (const float*)d_in[0];
    const int* ei = (const int*)d_in[1];
    const float* mapd = (const float*)d_in[2];
    const float* bl1 = (const float*)d_in[4];
    const float* bl2 = (const float*)d_in[7];
    const float* bl3 = (const float*)d_in[10];
    const float* k1 = (const float*)d_in[12];
    const float* cb1 = (const float*)d_in[13];
    const float* k2 = (const float*)d_in[14];
    const float* cb2 = (const float*)d_in[15];
    const float* Wm = (const float*)d_in[16];
    const float* bm = (const float*)d_in[17];
    const float* b1 = (const float*)d_in[19];
    const float* W2 = (const float*)d_in[20];
    const float* b2 = (const float*)d_in[21];
    float* out = (float*)d_out;

    cudaFuncSetAttribute(k_tgemm, cudaFuncAttributeMaxDynamicSharedMemorySize, TG_SMEM);

    void *p_cnt, *p_cg;
    void *p_mx, *p_wc1, *p_h1, *p_wc2, *p_pq2, *p_h2, *p_wc3, *p_pq3, *p_h3;
    void *p_w1p, *p_y1, *p_xcol, *p_hstats, *p_mnorm;
    cudaGetSymbolAddress(&p_cnt, d_cnt);
    cudaGetSymbolAddress(&p_cg, d_cg);
    cudaGetSymbolAddress(&p_mx, d_mx);
    cudaGetSymbolAddress(&p_wc1, d_wc1);
    cudaGetSymbolAddress(&p_h1, d_h1);
    cudaGetSymbolAddress(&p_wc2, d_wc2);
    cudaGetSymbolAddress(&p_pq2, d_pq2);
    cudaGetSymbolAddress(&p_h2, d_h2);
    cudaGetSymbolAddress(&p_wc3, d_wc3);
    cudaGetSymbolAddress(&p_pq3, d_pq3);
    cudaGetSymbolAddress(&p_h3, d_h3);
    cudaGetSymbolAddress(&p_w1p, d_w1p);
    cudaGetSymbolAddress(&p_y1, d_y1);
    cudaGetSymbolAddress(&p_xcol, d_xcol);
    cudaGetSymbolAddress(&p_hstats, d_hstats);
    cudaGetSymbolAddress(&p_mnorm, d_mnorm);

    // 1: memset(cnt)  2: memset(cg)
    cudaMemsetAsync(p_cnt, 0, NN * sizeof(int));
    cudaMemsetAsync(p_cg, 0, 896 * 128 * sizeof(float));

    // 3: packAll  4: conv1  5: im2col  6: conv2 tgemm (ncu target, -s 5 -c 1)
    k_packAll<<<447, 256>>>((const float*)d_in[3], (const float*)d_in[5],
                            (const float*)d_in[6], (const float*)d_in[8],
                            (const float*)d_in[9], (const float*)d_in[11],
                            (const float*)d_in[18]);
    k_conv1<<<(256 * 1573 + 255) / 256, 256>>>(mapd, k1, cb1);
    k_im2col<<<dim3(27, 891), 256>>>();
    k_tgemm<<<dim3(1, 7, 24), 256, TG_SMEM>>>((const float*)p_xcol, k2, (float*)p_cg,
                                              128, 6912, nullptr, nullptr, nullptr, 1);
    k_m2fin<<<(128 * 891 + 255) / 256, 256>>>(cb2);
    k_wm<<<dim3(64, 8), 256>>>(Wm);

    // CSR build
    k_degcnt<<<(NE + 255) / 256, 256>>>(ei);
    k_scan1<<<NB1, 256>>>();
    k_scan3<<<NB1, 256>>>();
    k_scatter<<<(NE + 255) / 256, 256>>>(ei);

    // layer 1 (K padded to 64)
    k_xpad<<<(NN * 32 + 255) / 256, 256>>>(node);
    k_aggA<<<(NN * 32 + 255) / 256, 256>>>();
    k_tgemm<<<dim3(2, 391, 1), 256, TG_SMEM>>>((const float*)p_mx, (const float*)p_wc1,
                                               (float*)p_h1, 256, 64,
                                               nullptr, nullptr, nullptr, 0);
    // layer 2
    k_tgemm<<<dim3(2, 391, 1), 256, TG_SMEM>>>((const float*)p_h1, (const float*)p_wc2,
                                               (float*)p_pq2, 256, 256,
                                               bl1, nullptr, nullptr, 0);
    k_aggB<<<(NN * 32 + 255) / 256, 256>>>(bl2);
    // layer 3
    k_tgemm<<<dim3(1, 391, 1), 256, TG_SMEM>>>((const float*)p_h2, (const float*)p_wc3,
                                               (float*)p_pq3, 128, 128,
                                               nullptr, nullptr, nullptr, 0);
    k_aggC<<<(NN * 16 + 255) / 256, 256>>>(bl3);

    // stats + head
    k_hred1<<<256, 256>>>();
    k_finstats<<<1, 256>>>(bm);
    k_tgemm<<<dim3(1, 391, 1), 256, TG_SMEM>>>((const float*)p_h3, (const float*)p_w1p,
                                               (float*)p_y1, 128, 64,
                                               nullptr, (const float*)p_hstats,
                                               (const float*)p_mnorm, 0);
    k_head<<<(NN + 255) / 256, 256>>>(W2, b2, b1, out);
}

// round 9
// speedup vs baseline: 1.1455x; 1.1451x over previous
#include <cuda_runtime.h>
#include <mma.h>
#include <math.h>

using namespace nvcuda;

#define NN 50000
#define MP 50048   // padded rows: 391 * 128
#define NE 800000
#define NB1 196    // ceil(NN/256)

// ---------------- scratch ----------------
static __device__ int   d_cnt[NN];
static __device__ int   d_rowptr[NN + 1];
static __device__ int   d_cursor[NN];
static __device__ int   d_csrc[NE];
static __device__ int   d_part[256];
static __device__ float d_xp[(size_t)NN * 32];
static __device__ float d_mx[(size_t)MP * 48];
static __device__ float d_wc1[256 * 48];
static __device__ float d_h1[(size_t)MP * 256];
static __device__ float d_wc2[256 * 256];
static __device__ float d_pq2[(size_t)MP * 256];  // [p(128)|q(128)]
static __device__ float d_h2[(size_t)MP * 128];
static __device__ float d_wc3[128 * 128];
static __device__ float d_pq3[(size_t)MP * 128];  // [p(64)|q(64)]
static __device__ float d_h3[(size_t)MP * 64];
static __device__ float d_w1p[128 * 64];
static __device__ float d_y1[(size_t)MP * 128];
static __device__ float d_m1[256 * 13 * 11 * 11];
static __device__ float d_xcol[(size_t)896 * 6912];
static __device__ float d_cg[896 * 128];
static __device__ float d_m2[128 * 891];
static __device__ float d_wmpart[8][64];
static __device__ float d_mnorm[64];
static __device__ float d_pmin[256];
static __device__ float d_pmax[256];
static __device__ float d_hstats[4];
static __device__ int   d_koff[6912];
static __device__ int   d_poff[896];

// ---------------- merged weight packing + im2col tables ----------------
__global__ void k_packAll(const float* __restrict__ Wl1, const float* __restrict__ Wr1,
                          const float* __restrict__ Wl2, const float* __restrict__ Wr2,
                          const float* __restrict__ Wl3, const float* __restrict__ Wr3,
                          const float* __restrict__ W1) {
    int i = blockIdx.x * blockDim.x + threadIdx.x;
    if (i < 12288) {
        int n = i / 48, f = i % 48;
        float v = 0.f;
        if (f < 21) v = Wl1[n * 21 + f];
        else if (f < 42) v = Wr1[n * 21 + (f - 21)];
        d_wc1[i] = v;
    } else if (i < 77824) {
        int j = i - 12288;
        int n = j / 256, f = j % 256;
        d_wc2[j] = (n < 128) ? Wl2[n * 256 + f] : Wr2[(n - 128) * 256 + f];
    } else if (i < 94208) {
        int j = i - 77824;
        int n = j / 128, f = j % 128;
        d_wc3[j] = (n < 64) ? Wl3[n * 128 + f] : Wr3[(n - 64) * 128 + f];
    } else if (i < 102400) {
        int j = i - 94208;
        int n = j / 64;
        d_w1p[j] = (n < 64) ? W1[j] : 0.f;
    } else if (i < 109312) {
        int j = i - 102400;
        int ic = j / 27, tap = j % 27;
        int kd = tap / 9, r = tap % 9, kh = r / 3, kw = r % 3;
        d_koff[j] = ic * 1573 + kd * 121 + kh * 11 + kw;
    } else if (i < 110208) {
        int j = i - 109312;
        int v = 0;
        if (j < 891) {
            int od = j / 81, r2 = j % 81, oh = r2 / 9, ow = r2 % 9;
            v = od * 121 + oh * 11 + ow;
        }
        d_poff[j] = v;
    }
}

// ---------------- CSR build ----------------
__global__ void k_degcnt(const int* __restrict__ ei) {
    int e = blockIdx.x * blockDim.x + threadIdx.x;
    if (e < NE) atomicAdd(&d_cnt[ei[NE + e]], 1);
}
__global__ void k_scan1() {
    __shared__ int sh[256];
    int t = threadIdx.x;
    int i = blockIdx.x * 256 + t;
    int v = (i < NN) ? d_cnt[i] : 0;
    sh[t] = v;
    __syncthreads();
#pragma unroll
    for (int off = 1; off < 256; off <<= 1) {
        int a = (t >= off) ? sh[t - off] : 0;
        __syncthreads();
        sh[t] += a;
        __syncthreads();
    }
    if (i < NN) d_rowptr[i] = sh[t] - v;
    if (t == 255) d_part[blockIdx.x] = sh[255];
}
__global__ void k_scan3() {
    __shared__ int sh[256];
    int t = threadIdx.x;
    int v = (t < NB1) ? d_part[t] : 0;
    sh[t] = v;
    __syncthreads();
#pragma unroll
    for (int off = 1; off < 256; off <<= 1) {
        int a = (t >= off) ? sh[t - off] : 0;
        __syncthreads();
        sh[t] += a;
        __syncthreads();
    }
    int base = (blockIdx.x > 0) ? sh[blockIdx.x - 1] : 0;
    int i = blockIdx.x * 256 + t;
    if (i < NN) {
        int r = d_rowptr[i] + base;
        d_rowptr[i] = r;
        d_cursor[i] = r;
    }
    if (i == 0) d_rowptr[NN] = NE;
}
__global__ void k_scatter(const int* __restrict__ ei) {
    int e = blockIdx.x * blockDim.x + threadIdx.x;
    if (e >= NE) return;
    int s = ei[e], d = ei[NE + e];
    int pos = atomicAdd(&d_cursor[d], 1);
    d_csrc[pos] = s;
}

// ---------------- node feature pad + aggregation ----------------
__global__ void k_xpad(const float* __restrict__ x) {
    int idx = blockIdx.x * blockDim.x + threadIdx.x;
    if (idx >= NN * 32) return;
    int n = idx >> 5, f = idx & 31;
    d_xp[idx] = (f < 21) ? x[n * 21 + f] : 0.f;
}
__global__ void k_aggA() {
    int w = (blockIdx.x * blockDim.x + threadIdx.x) >> 5;
    int lane = threadIdx.x & 31;
    if (w >= NN) return;
    int beg = d_rowptr[w], end = d_rowptr[w + 1];
    float acc = 0.f;
    int e = beg;
    for (; e + 4 <= end; e += 4) {
        int s0 = __ldg(&d_csrc[e]);
        int s1 = __ldg(&d_csrc[e + 1]);
        int s2 = __ldg(&d_csrc[e + 2]);
        int s3 = __ldg(&d_csrc[e + 3]);
        acc += d_xp[(size_t)s0 * 32 + lane] + d_xp[(size_t)s1 * 32 + lane] +
               d_xp[(size_t)s2 * 32 + lane] + d_xp[(size_t)s3 * 32 + lane];
    }
    for (; e < end; e++) acc += d_xp[(size_t)__ldg(&d_csrc[e]) * 32 + lane];
    float inv = 1.f / fmaxf((float)(end - beg), 1.0f);
    if (lane < 21) {
        d_mx[(size_t)w * 48 + lane] = acc * inv;
        d_mx[(size_t)w * 48 + 21 + lane] = d_xp[(size_t)w * 32 + lane];
    } else if (lane < 27) {
        d_mx[(size_t)w * 48 + 21 + lane] = 0.f;
    }
}
__global__ void k_aggB(const float* __restrict__ bl) {
    int w = (blockIdx.x * blockDim.x + threadIdx.x) >> 5;
    int lane = threadIdx.x & 31;
    if (w >= NN) return;
    int beg = d_rowptr[w], end = d_rowptr[w + 1];
    const float4* pq = (const float4*)d_pq2;
    float4 acc = make_float4(0.f, 0.f, 0.f, 0.f);
#pragma unroll 4
    for (int e = beg; e < end; e++) {
        int s = __ldg(&d_csrc[e]);
        float4 v = pq[(size_t)s * 64 + lane];
        acc.x += v.x; acc.y += v.y; acc.z += v.z; acc.w += v.w;
    }
    float inv = 1.f / fmaxf((float)(end - beg), 1.0f);
    float4 q = pq[(size_t)w * 64 + 32 + lane];
    float4 b = ((const float4*)bl)[lane];
    float4 o;
    o.x = fmaxf(acc.x * inv + b.x + q.x, 0.f);
    o.y = fmaxf(acc.y * inv + b.y + q.y, 0.f);
    o.z = fmaxf(acc.z * inv + b.z + q.z, 0.f);
    o.w = fmaxf(acc.w * inv + b.w + q.w, 0.f);
    ((float4*)d_h2)[(size_t)w * 32 + lane] = o;
}
__global__ void k_aggC(const float* __restrict__ bl) {
    int g = (blockIdx.x * blockDim.x + threadIdx.x) >> 4;
    int lane = threadIdx.x & 15;
    if (g >= NN) return;
    int beg = d_rowptr[g], end = d_rowptr[g + 1];
    const float4* pq = (const float4*)d_pq3;
    float4 acc = make_float4(0.f, 0.f, 0.f, 0.f);
#pragma unroll 4
    for (int e = beg; e < end; e++) {
        int s = __ldg(&d_csrc[e]);
        float4 v = pq[(size_t)s * 32 + lane];
        acc.x += v.x; acc.y += v.y; acc.z += v.z; acc.w += v.w;
    }
    float inv = 1.f / fmaxf((float)(end - beg), 1.0f);
    float4 q = pq[(size_t)g * 32 + 16 + lane];
    float4 b = ((const float4*)bl)[lane];
    float4 o;
    o.x = acc.x * inv + b.x + q.x;
    o.y = acc.y * inv + b.y + q.y;
    o.z = acc.z * inv + b.z + q.z;
    o.w = acc.w * inv + b.w + q.w;
    ((float4*)d_h3)[(size_t)g * 16 + lane] = o;
}

// ---------------- tf32 tensor-core GEMM (round-6 proven version) ----------------
__global__ void __launch_bounds__(256, 2) k_tgemm(
    const float* __restrict__ A, const float* __restrict__ B, float* __restrict__ C,
    int N, int K, const float* __restrict__ abias,
    const float* __restrict__ xstats, const float* __restrict__ madd, int split) {
    __shared__ float As[2][128][20];
    __shared__ float Bs[2][128][20];
    int tid = threadIdx.x;
    int wid = tid >> 5;
    int lane = tid & 31;
    int bm = blockIdx.y * 128;
    int bn = blockIdx.x * 128;
    int wm = (wid >> 2) * 64;
    int wn = (wid & 3) * 32;
    int lrow = tid >> 1;
    int lcol = (tid & 1) * 8;
    int nkz = (K / 16) / gridDim.z;
    int kbase = blockIdx.z * nkz * 16;

    float hs0 = 0.f, hs1 = 0.f;
    if (xstats) { hs0 = xstats[0]; hs1 = xstats[1]; }

    wmma::fragment<wmma::accumulator, 16, 16, 8, float> cf[4][2];
#pragma unroll
    for (int i = 0; i < 4; i++)
#pragma unroll
        for (int j = 0; j < 2; j++) wmma::fill_fragment(cf[i][j], 0.f);

    const float* Arow = A + (size_t)(bm + lrow) * K + kbase + lcol;
    const float* Brow = B + (size_t)(bn + lrow) * K + kbase + lcol;

    float4 a0, a1, b0v, b1v;

#define CVT4(v)                                                                 \
    do {                                                                        \
        v.x = wmma::__float_to_tf32(v.x); v.y = wmma::__float_to_tf32(v.y);     \
        v.z = wmma::__float_to_tf32(v.z); v.w = wmma::__float_to_tf32(v.w);     \
    } while (0)

#define LOADTILE(koff)                                                          \
    do {                                                                        \
        a0 = *(const float4*)(Arow + (koff));                                   \
        a1 = *(const float4*)(Arow + (koff) + 4);                               \
        b0v = *(const float4*)(Brow + (koff));                                  \
        b1v = *(const float4*)(Brow + (koff) + 4);                              \
        if (abias) {                                                            \
            const float* bp = abias + kbase + (koff) + lcol;                    \
            a0.x = fmaxf(a0.x + bp[0], 0.f); a0.y = fmaxf(a0.y + bp[1], 0.f);   \
            a0.z = fmaxf(a0.z + bp[2], 0.f); a0.w = fmaxf(a0.w + bp[3], 0.f);   \
            a1.x = fmaxf(a1.x + bp[4], 0.f); a1.y = fmaxf(a1.y + bp[5], 0.f);   \
            a1.z = fmaxf(a1.z + bp[6], 0.f); a1.w = fmaxf(a1.w + bp[7], 0.f);   \
        } else if (xstats) {                                                    \
            const float* mp = madd + kbase + (koff) + lcol;                     \
            a0.x = hs0 * a0.x + hs1 + mp[0]; a0.y = hs0 * a0.y + hs1 + mp[1];   \
            a0.z = hs0 * a0.z + hs1 + mp[2]; a0.w = hs0 * a0.w + hs1 + mp[3];   \
            a1.x = hs0 * a1.x + hs1 + mp[4]; a1.y = hs0 * a1.y + hs1 + mp[5];   \
            a1.z = hs0 * a1.z + hs1 + mp[6]; a1.w = hs0 * a1.w + hs1 + mp[7];   \
        }                                                                       \
        CVT4(a0); CVT4(a1); CVT4(b0v); CVT4(b1v);                               \
    } while (0)

#define STORETILE(bi)                                                           \
    do {                                                                        \
        *(float4*)&As[bi][lrow][lcol] = a0;                                     \
        *(float4*)&As[bi][lrow][lcol + 4] = a1;                                 \
        *(float4*)&Bs[bi][lrow][lcol] = b0v;                                    \
        *(float4*)&Bs[bi][lrow][lcol + 4] = b1v;                                \
    } while (0)

    LOADTILE(0);
    STORETILE(0);
    __syncthreads();

    for (int it = 0; it < nkz; it++) {
        int buf = it & 1;
        bool more = (it + 1) < nkz;
        if (more) LOADTILE((it + 1) * 16);
#pragma unroll
        for (int ks = 0; ks < 16; ks += 8) {
            wmma::fragment<wmma::matrix_a, 16, 16, 8, wmma::precision::tf32, wmma::row_major> af[4];
            wmma::fragment<wmma::matrix_b, 16, 16, 8, wmma::precision::tf32, wmma::col_major> bf[2];
#pragma unroll
            for (int i = 0; i < 4; i++)
                wmma::load_matrix_sync(af[i], &As[buf][wm + i * 16][ks], 20);
#pragma unroll
            for (int j = 0; j < 2; j++)
                wmma::load_matrix_sync(bf[j], &Bs[buf][wn + j * 16][ks], 20);
#pragma unroll
            for (int i = 0; i < 4; i++)
#pragma unroll
                for (int j = 0; j < 2; j++)
                    wmma::mma_sync(cf[i][j], af[i], bf[j], cf[i][j]);
        }
        if (more) STORETILE(1 - buf);
        __syncthreads();
    }

    if (!split) {
#pragma unroll
        for (int i = 0; i < 4; i++)
#pragma unroll
            for (int j = 0; j < 2; j++)
                wmma::store_matrix_sync(&C[(size_t)(bm + wm + i * 16) * N + bn + wn + j * 16],
                                        cf[i][j], N, wmma::mem_row_major);
    } else {
        float* stage = &As[0][0][0] + wid * 320;
#pragma unroll
        for (int i = 0; i < 4; i++)
#pragma unroll
            for (int j = 0; j < 2; j++) {
                wmma::store_matrix_sync(stage, cf[i][j], 20, wmma::mem_row_major);
                __syncwarp();
                float* cp = &C[(size_t)(bm + wm + i * 16) * N + bn + wn + j * 16];
#pragma unroll
                for (int e = 0; e < 8; e++) {
                    int idx = lane * 8 + e;
                    int r = idx >> 4, c = idx & 15;
                    atomicAdd(&cp[(size_t)r * N + c], stage[r * 20 + c]);
                }
                __syncwarp();
            }
    }
#undef LOADTILE
#undef STORETILE
#undef CVT4
}

// ---------------- map encoder ----------------
__global__ void k_conv1(const float* __restrict__ in, const float* __restrict__ w,
                        const float* __restrict__ b) {
    int idx = blockIdx.x * blockDim.x + threadIdx.x;
    if (idx >= 256 * 1573) return;
    int oc = idx / 1573, p = idx % 1573;
    int od = p / 121, r = p % 121, oh = r / 11, ow = r % 11;
    const float* wp = w + oc * 75;
    float acc = 0.f;
#pragma unroll
    for (int kd = 0; kd < 3; kd++)
#pragma unroll
        for (int kh = 0; kh < 5; kh++)
#pragma unroll
            for (int kw = 0; kw < 5; kw++)
                acc += in[(od + kd) * 225 + (oh + kh) * 15 + (ow + kw)] *
                       wp[kd * 25 + kh * 5 + kw];
    d_m1[idx] = fmaxf(acc + b[oc], 0.f);
}

__global__ void k_im2col() {
    int k = blockIdx.x * 256 + threadIdx.x;
    int pos = blockIdx.y;
    d_xcol[(size_t)pos * 6912 + k] = d_m1[d_koff[k] + d_poff[pos]];
}

__global__ void k_m2fin(const float* __restrict__ cb2) {
    int idx = blockIdx.x * blockDim.x + threadIdx.x;
    if (idx >= 128 * 891) return;
    int oc = idx / 891, pos = idx % 891;
    d_m2[idx] = fmaxf(d_cg[(size_t)pos * 128 + oc] + cb2[oc], 0.f);
}

__global__ void k_wm(const float* __restrict__ Wm) {
    __shared__ float red[256];
    int o = blockIdx.x;
    int chunk = blockIdx.y;
    const int CH = 114048 / 8;
    int base = chunk * CH;
    const float* wr = Wm + (size_t)o * 114048 + base;
    const float* mv = d_m2 + base;
    float s = 0.f;
    for (int i = threadIdx.x * 4; i < CH; i += 256 * 4) {
        float4 a = *(const float4*)(wr + i);
        float4 v = *(const float4*)(mv + i);
        s += a.x * v.x + a.y * v.y + a.z * v.z + a.w * v.w;
    }
    red[threadIdx.x] = s;
    __syncthreads();
    for (int st = 128; st > 0; st >>= 1) {
        if (threadIdx.x < st) red[threadIdx.x] += red[threadIdx.x + st];
        __syncthreads();
    }
    if (threadIdx.x == 0) d_wmpart[chunk][o] = red[0];
}

// ---------------- h3 min/max ----------------
__global__ void k_hred1() {
    __shared__ float smn[256], smx[256];
    int tid = threadIdx.x;
    float mn = 3.4e38f, mx = -3.4e38f;
    for (size_t i = (size_t)blockIdx.x * 256 + tid; i < (size_t)NN * 64; i += (size_t)256 * 256) {
        float v = d_h3[i];
        mn = fminf(mn, v); mx = fmaxf(mx, v);
    }
    smn[tid] = mn; smx[tid] = mx;
    __syncthreads();
    for (int st = 128; st > 0; st >>= 1) {
        if (tid < st) {
            smn[tid] = fminf(smn[tid], smn[tid + st]);
            smx[tid] = fmaxf(smx[tid], smx[tid + st]);
        }
        __syncthreads();
    }
    if (tid == 0) { d_pmin[blockIdx.x] = smn[0]; d_pmax[blockIdx.x] = smx[0]; }
}
__global__ void k_finstats(const float* __restrict__ bm) {
    __shared__ float smn[256], smx[256];
    int t = threadIdx.x;
    smn[t] = d_pmin[t]; smx[t] = d_pmax[t];
    __syncthreads();
    for (int st = 128; st > 0; st >>= 1) {
        if (t < st) {
            smn[t] = fminf(smn[t], smn[t + st]);
            smx[t] = fmaxf(smx[t], smx[t + st]);
        }
        __syncthreads();
    }
    if (t == 0) {
        float mn = smn[0], mx = smx[0];
        float a = 0.35f / (mx - mn);
        d_hstats[0] = a;
        d_hstats[1] = -mn * a;
    }
    __syncthreads();
    float v = 0.f;
    if (t < 64) {
        v = bm[t];
#pragma unroll
        for (int c = 0; c < 8; c++) v += d_wmpart[c][t];
    }
    smn[t] = (t < 64) ? v : 3.4e38f;
    smx[t] = (t < 64) ? v : -3.4e38f;
    __syncthreads();
    for (int st = 128; st > 0; st >>= 1) {
        if (t < st) {
            smn[t] = fminf(smn[t], smn[t + st]);
            smx[t] = fmaxf(smx[t], smx[t + st]);
        }
        __syncthreads();
    }
    if (t < 64) {
        float mn = smn[0], mx = smx[0];
        d_mnorm[t] = 0.65f * (v - mn) / (mx - mn);
    }
}

// ---------------- final layer + softmax ----------------
__global__ void k_head(const float* __restrict__ W2, const float* __restrict__ b2,
                       const float* __restrict__ b1, float* __restrict__ out) {
    __shared__ float w2s[3][64];
    __shared__ float b2s[3];
    __shared__ float b1s[64];
    int tid = threadIdx.x;
    if (tid < 192) w2s[tid / 64][tid % 64] = W2[tid];
    if (tid < 3) b2s[tid] = b2[tid];
    if (tid >= 192 && tid < 256) b1s[tid - 192] = b1[tid - 192];
    __syncthreads();
    int i = blockIdx.x * blockDim.x + tid;
    if (i >= NN) return;
    const float* y = d_y1 + (size_t)i * 128;
    float s0 = b2s[0], s1 = b2s[1], s2 = b2s[2];
#pragma unroll
    for (int f = 0; f < 64; f += 4) {
        float4 v = *(const float4*)(y + f);
        v.x = fmaxf(v.x + b1s[f], 0.f);
        v.y = fmaxf(v.y + b1s[f + 1], 0.f);
        v.z = fmaxf(v.z + b1s[f + 2], 0.f);
        v.w = fmaxf(v.w + b1s[f + 3], 0.f);
        s0 += v.x * w2s[0][f] + v.y * w2s[0][f + 1] + v.z * w2s[0][f + 2] + v.w * w2s[0][f + 3];
        s1 += v.x * w2s[1][f] + v.y * w2s[1][f + 1] + v.z * w2s[1][f + 2] + v.w * w2s[1][f + 3];
        s2 += v.x * w2s[2][f] + v.y * w2s[2][f + 1] + v.z * w2s[2][f + 2] + v.w * w2s[2][f + 3];
    }
    float m = fmaxf(s0, fmaxf(s1, s2));
    float e0 = expf(s0 - m), e1 = expf(s1 - m), e2 = expf(s2 - m);
    float inv = 1.f / (e0 + e1 + e2);
    out[(size_t)i * 3 + 0] = e0 * inv;
    out[(size_t)i * 3 + 1] = e1 * inv;
    out[(size_t)i * 3 + 2] = e2 * inv;
}

// ---------------- launch ----------------
extern "C" void kernel_launch(void* const* d_in, const int* in_sizes, int n_in,
                              void* d_out, int out_size) {
    (void)in_sizes; (void)n_in; (void)out_size;
    const float* node = (const float*)d_in[0];
    const int* ei = (const int*)d_in[1];
    const float* mapd = (const float*)d_in[2];
    const float* bl1 = (const float*)d_in[4];
    const float* bl2 = (const float*)d_in[7];
    const float* bl3 = (const float*)d_in[10];
    const float* k1 = (const float*)d_in[12];
    const float* cb1 = (const float*)d_in[13];
    const float* k2 = (const float*)d_in[14];
    const float* cb2 = (const float*)d_in[15];
    const float* Wm = (const float*)d_in[16];
    const float* bm = (const float*)d_in[17];
    const float* b1 = (const float*)d_in[19];
    const float* W2 = (const float*)d_in[20];
    const float* b2 = (const float*)d_in[21];
    float* out = (float*)d_out;

    void *p_cnt, *p_cg;
    void *p_mx, *p_wc1, *p_h1, *p_wc2, *p_pq2, *p_h2, *p_wc3, *p_pq3, *p_h3;
    void *p_w1p, *p_y1, *p_xcol, *p_hstats, *p_mnorm;
    cudaGetSymbolAddress(&p_cnt, d_cnt);
    cudaGetSymbolAddress(&p_cg, d_cg);
    cudaGetSymbolAddress(&p_mx, d_mx);
    cudaGetSymbolAddress(&p_wc1, d_wc1);
    cudaGetSymbolAddress(&p_h1, d_h1);
    cudaGetSymbolAddress(&p_wc2, d_wc2);
    cudaGetSymbolAddress(&p_pq2, d_pq2);
    cudaGetSymbolAddress(&p_h2, d_h2);
    cudaGetSymbolAddress(&p_wc3, d_wc3);
    cudaGetSymbolAddress(&p_pq3, d_pq3);
    cudaGetSymbolAddress(&p_h3, d_h3);
    cudaGetSymbolAddress(&p_w1p, d_w1p);
    cudaGetSymbolAddress(&p_y1, d_y1);
    cudaGetSymbolAddress(&p_xcol, d_xcol);
    cudaGetSymbolAddress(&p_hstats, d_hstats);
    cudaGetSymbolAddress(&p_mnorm, d_mnorm);

    // Side stream + fork/join events (host objects only; capture-legal pattern)
    cudaStream_t s2;
    cudaStreamCreateWithFlags(&s2, cudaStreamNonBlocking);
    cudaEvent_t evFork, evJoin;
    cudaEventCreateWithFlags(&evFork, cudaEventDisableTiming);
    cudaEventCreateWithFlags(&evJoin, cudaEventDisableTiming);

    // 1: memset(cnt)  2: memset(cg)  3: packAll   (main stream)
    cudaMemsetAsync(p_cnt, 0, NN * sizeof(int));
    cudaMemsetAsync(p_cg, 0, 896 * 128 * sizeof(float));
    k_packAll<<<431, 256>>>((const float*)d_in[3], (const float*)d_in[5],
                            (const float*)d_in[6], (const float*)d_in[8],
                            (const float*)d_in[9], (const float*)d_in[11],
                            (const float*)d_in[18]);

    // fork conv path onto s2
    cudaEventRecord(evFork, 0);
    cudaStreamWaitEvent(s2, evFork, 0);

    // conv path on s2: 4 conv1, 5 im2col, 6 conv2 tgemm (ncu target), 7 m2fin, 8 wm
    k_conv1<<<(256 * 1573 + 255) / 256, 256, 0, s2>>>(mapd, k1, cb1);
    k_im2col<<<dim3(27, 891), 256, 0, s2>>>();
    k_tgemm<<<dim3(1, 7, 16), 256, 0, s2>>>((const float*)p_xcol, k2, (float*)p_cg,
                                            128, 6912, nullptr, nullptr, nullptr, 1);
    k_m2fin<<<(128 * 891 + 255) / 256, 256, 0, s2>>>(cb2);
    k_wm<<<dim3(64, 8), 256, 0, s2>>>(Wm);
    cudaEventRecord(evJoin, s2);

    // GNN path on main stream (overlaps with s2)
    k_degcnt<<<(NE + 255) / 256, 256>>>(ei);
    k_scan1<<<NB1, 256>>>();
    k_scan3<<<NB1, 256>>>();
    k_scatter<<<(NE + 255) / 256, 256>>>(ei);

    k_xpad<<<(NN * 32 + 255) / 256, 256>>>(node);
    k_aggA<<<(NN * 32 + 255) / 256, 256>>>();
    k_tgemm<<<dim3(2, 391, 1), 256>>>((const float*)p_mx, (const float*)p_wc1,
                                      (float*)p_h1, 256, 48,
                                      nullptr, nullptr, nullptr, 0);
    k_tgemm<<<dim3(2, 391, 1), 256>>>((const float*)p_h1, (const float*)p_wc2,
                                      (float*)p_pq2, 256, 256,
                                      bl1, nullptr, nullptr, 0);
    k_aggB<<<(NN * 32 + 255) / 256, 256>>>(bl2);
    k_tgemm<<<dim3(1, 391, 1), 256>>>((const float*)p_h2, (const float*)p_wc3,
                                      (float*)p_pq3, 128, 128,
                                      nullptr, nullptr, nullptr, 0);
    k_aggC<<<(NN * 16 + 255) / 256, 256>>>(bl3);

    k_hred1<<<256, 256>>>();

    // join conv path before finstats (needs d_wmpart)
    cudaStreamWaitEvent(0, evJoin, 0);
    k_finstats<<<1, 256>>>(bm);
    k_tgemm<<<dim3(1, 391, 1), 256>>>((const float*)p_h3, (const float*)p_w1p,
                                      (float*)p_y1, 128, 64,
                                      nullptr, (const float*)p_hstats,
                                      (const float*)p_mnorm, 0);
    k_head<<<(NN + 255) / 256, 256>>>(W2, b2, b1, out);

    cudaEventDestroy(evFork);
    cudaEventDestroy(evJoin);
    cudaStreamDestroy(s2);
}